// round 6
// baseline (speedup 1.0000x reference)
#include <cuda_runtime.h>
#include <cuda_fp16.h>
#include <math.h>

// Problem constants
#define NN      100000
#define EE      1600000
#define INDIM   128
#define HIDD    64
#define NHEADS  4
#define ODIM    64

// ---------------------------------------------------------------------------
// Scratch (device globals — the sanctioned no-alloc path)
// ---------------------------------------------------------------------------
__device__ __half g_bufH[(size_t)NN * 256];  // GEMM outputs h (fp16)
__device__ float  g_bufB[(size_t)NN * 256];  // agg outputs / rounded x (f32)
__device__ float  g_wr[128*256 + 256*256 + 256*64];   // tf32-rounded weights
__device__ float  g_alphaS[NN * NHEADS];
__device__ float  g_alphaD[NN * NHEADS];
__device__ int    g_rowptr[NN + 1];
__device__ int    g_fill[NN];
__device__ int    g_csr_src[EE];
__device__ int    g_bsums[128];

__device__ __forceinline__ unsigned f2tf(float x) {
    unsigned r;
    asm("cvt.rna.tf32.f32 %0, %1;" : "=r"(r) : "f"(x));
    return r;
}

// ---------------------------------------------------------------------------
// tf32 pre-rounding pass (idempotent: values are re-truncated at MMA anyway)
// dstSel: 1=bufB, 2=g_wr
// ---------------------------------------------------------------------------
__global__ void k_round(const float* __restrict__ src, int dstSel, int dstOff, int n)
{
    float* dst = (dstSel == 2 ? g_wr : g_bufB) + dstOff;
    int i = blockIdx.x * blockDim.x + threadIdx.x;
    int stride = gridDim.x * blockDim.x;
    for (; i < n; i += stride)
        dst[i] = __uint_as_float(f2tf(src[i]));
}

// ---------------------------------------------------------------------------
// CSR build: histogram -> exclusive scan -> scatter
// ---------------------------------------------------------------------------
__global__ void k_zero_fill() {
    int i = blockIdx.x * blockDim.x + threadIdx.x;
    if (i < NN) g_fill[i] = 0;
}

__global__ void k_hist(const int* __restrict__ ei) {
    int e = blockIdx.x * blockDim.x + threadIdx.x;
    if (e < EE) atomicAdd(&g_fill[ei[EE + e]], 1);
}

__global__ void k_scan1() {
    __shared__ int s[1024];
    int t = threadIdx.x;
    int i = blockIdx.x * 1024 + t;
    int v = (i < NN) ? g_fill[i] : 0;
    s[t] = v;
    __syncthreads();
    #pragma unroll
    for (int off = 1; off < 1024; off <<= 1) {
        int add = (t >= off) ? s[t - off] : 0;
        __syncthreads();
        s[t] += add;
        __syncthreads();
    }
    if (i < NN) g_rowptr[i] = s[t] - v;   // exclusive
    if (t == 1023) g_bsums[blockIdx.x] = s[1023];
}

__global__ void k_scan2(int nb) {
    if (threadIdx.x == 0 && blockIdx.x == 0) {
        int run = 0;
        for (int b = 0; b < nb; b++) { int v = g_bsums[b]; g_bsums[b] = run; run += v; }
        g_rowptr[NN] = run;   // == EE
    }
}

__global__ void k_scan3() {
    int i = blockIdx.x * 1024 + threadIdx.x;
    if (i < NN) g_rowptr[i] += g_bsums[blockIdx.x];
}

__global__ void k_scatter(const int* __restrict__ ei) {
    int e = blockIdx.x * blockDim.x + threadIdx.x;
    if (e < EE) {
        int d   = ei[EE + e];
        int pos = g_rowptr[d] + atomicAdd(&g_fill[d], 1);
        g_csr_src[pos] = ei[e];
    }
}

// ---------------------------------------------------------------------------
// TF32 tensor-core GEMM + fused alpha epilogue, fp16 C output.
// ---------------------------------------------------------------------------
__device__ __forceinline__ void mma_tf32(float* c, const unsigned* a, const unsigned* b) {
    asm volatile(
        "mma.sync.aligned.m16n8k8.row.col.f32.tf32.tf32.f32 "
        "{%0,%1,%2,%3}, {%4,%5,%6,%7}, {%8,%9}, {%0,%1,%2,%3};\n"
        : "+f"(c[0]), "+f"(c[1]), "+f"(c[2]), "+f"(c[3])
        : "r"(a[0]), "r"(a[1]), "r"(a[2]), "r"(a[3]), "r"(b[0]), "r"(b[1]));
}

__device__ __forceinline__ void cp16(void* smem, const void* gmem, bool pred) {
    unsigned saddr = (unsigned)__cvta_generic_to_shared(smem);
    int sz = pred ? 16 : 0;   // src-size 0 => zero-fill, no global access
    asm volatile("cp.async.cg.shared.global [%0], [%1], 16, %2;\n"
                 :: "r"(saddr), "l"(gmem), "r"(sz));
}

__global__ void __launch_bounds__(256)
k_gemm_tf32(int wOff, const float* __restrict__ aVec, int heads,
            int M, int Ncols, int K)
{
    const float* A = g_bufB;
    const float* B = g_wr + wOff;
    __half* C = g_bufH;

    __shared__ float As[2][128][20];   // [stage][m][k]
    __shared__ float Bs[2][16][72];    // [stage][k][n]
    __shared__ float a_sh[128];        // a_s (0..63) | a_d (64..127) for this head
    __shared__ float sAl[128], dAl[128];

    int tid  = threadIdx.x;
    int lane = tid & 31;
    int wid  = tid >> 5;
    int warp_m = wid & 3;     // 0..3, 32 rows each
    int warp_n = wid >> 2;    // 0..1, 32 cols each
    int rowBase = blockIdx.y * 128;
    int colBase = blockIdx.x * 64;
    int head    = blockIdx.x;

    if (tid < 128) {
        a_sh[tid] = aVec[head * 128 + tid];
        sAl[tid] = 0.f;
        dAl[tid] = 0.f;
    }

    int ar = tid >> 2;          // 0..63 (rows ar and ar+64)
    int ak = (tid & 3) * 4;     // 0,4,8,12
    int br = tid >> 4;          // 0..15
    int bc = (tid & 15) * 4;    // 0..60

    const float* aSrc0 = A + (size_t)(rowBase + ar) * K + ak;
    const float* aSrc1 = A + (size_t)(rowBase + ar + 64) * K + ak;
    const float* bSrc  = B + (size_t)br * Ncols + colBase + bc;
    bool aOk0 = (rowBase + ar)      < M;
    bool aOk1 = (rowBase + ar + 64) < M;

    float acc[2][4][4];
    #pragma unroll
    for (int mt = 0; mt < 2; mt++)
        #pragma unroll
        for (int nt = 0; nt < 4; nt++)
            #pragma unroll
            for (int i = 0; i < 4; i++) acc[mt][nt][i] = 0.f;

    int nIter = K >> 4;

    cp16(&As[0][ar][ak],      aSrc0, aOk0);
    cp16(&As[0][ar + 64][ak], aSrc1, aOk1);
    cp16(&Bs[0][br][bc],      bSrc,  true);
    asm volatile("cp.async.commit_group;\n" ::: "memory");

    for (int it = 0; it < nIter; it++) {
        int s = it & 1;
        if (it + 1 < nIter) {
            int k0n = (it + 1) << 4;
            cp16(&As[s ^ 1][ar][ak],      aSrc0 + k0n, aOk0);
            cp16(&As[s ^ 1][ar + 64][ak], aSrc1 + k0n, aOk1);
            cp16(&Bs[s ^ 1][br][bc],      bSrc + (size_t)k0n * Ncols, true);
            asm volatile("cp.async.commit_group;\n" ::: "memory");
            asm volatile("cp.async.wait_group 1;\n" ::: "memory");
        } else {
            asm volatile("cp.async.wait_group 0;\n" ::: "memory");
        }
        __syncthreads();

        #pragma unroll
        for (int kk = 0; kk < 16; kk += 8) {
            unsigned af[2][4], bf[4][2];
            #pragma unroll
            for (int mt = 0; mt < 2; mt++) {
                int r0 = warp_m * 32 + mt * 16 + (lane >> 2);
                int kc = kk + (lane & 3);
                af[mt][0] = __float_as_uint(As[s][r0][kc]);
                af[mt][1] = __float_as_uint(As[s][r0 + 8][kc]);
                af[mt][2] = __float_as_uint(As[s][r0][kc + 4]);
                af[mt][3] = __float_as_uint(As[s][r0 + 8][kc + 4]);
            }
            #pragma unroll
            for (int nt = 0; nt < 4; nt++) {
                int cn = warp_n * 32 + nt * 8 + (lane >> 2);
                bf[nt][0] = __float_as_uint(Bs[s][kk + (lane & 3)][cn]);
                bf[nt][1] = __float_as_uint(Bs[s][kk + (lane & 3) + 4][cn]);
            }
            #pragma unroll
            for (int mt = 0; mt < 2; mt++)
                #pragma unroll
                for (int nt = 0; nt < 4; nt++)
                    mma_tf32(acc[mt][nt], af[mt], bf[nt]);
        }
        __syncthreads();
    }

    // ---- Epilogue: store C (fp16) + fused alpha (f32 acc) ----
    float s_part[2][2] = {{0.f,0.f},{0.f,0.f}};
    float d_part[2][2] = {{0.f,0.f},{0.f,0.f}};

    #pragma unroll
    for (int mt = 0; mt < 2; mt++) {
        int r0 = rowBase + warp_m * 32 + mt * 16 + (lane >> 2);
        #pragma unroll
        for (int nt = 0; nt < 4; nt++) {
            int cn = warp_n * 32 + nt * 8 + (lane & 3) * 2;   // block-local col
            int c0 = colBase + cn;
            if (r0 < M) {
                __half2 v = __floats2half2_rn(acc[mt][nt][0], acc[mt][nt][1]);
                *(__half2*)(C + (size_t)r0 * Ncols + c0) = v;
            }
            if (r0 + 8 < M) {
                __half2 v = __floats2half2_rn(acc[mt][nt][2], acc[mt][nt][3]);
                *(__half2*)(C + (size_t)(r0 + 8) * Ncols + c0) = v;
            }
            float as0 = a_sh[cn], as1 = a_sh[cn + 1];
            float ad0 = a_sh[64 + cn], ad1 = a_sh[64 + cn + 1];
            s_part[mt][0] += acc[mt][nt][0] * as0 + acc[mt][nt][1] * as1;
            d_part[mt][0] += acc[mt][nt][0] * ad0 + acc[mt][nt][1] * ad1;
            s_part[mt][1] += acc[mt][nt][2] * as0 + acc[mt][nt][3] * as1;
            d_part[mt][1] += acc[mt][nt][2] * ad0 + acc[mt][nt][3] * ad1;
        }
    }
    #pragma unroll
    for (int mt = 0; mt < 2; mt++)
        #pragma unroll
        for (int sl = 0; sl < 2; sl++) {
            #pragma unroll
            for (int o = 1; o < 4; o <<= 1) {
                s_part[mt][sl] += __shfl_xor_sync(0xffffffffu, s_part[mt][sl], o);
                d_part[mt][sl] += __shfl_xor_sync(0xffffffffu, d_part[mt][sl], o);
            }
        }
    if ((lane & 3) == 0) {
        #pragma unroll
        for (int mt = 0; mt < 2; mt++) {
            int rloc = warp_m * 32 + mt * 16 + (lane >> 2);
            atomicAdd(&sAl[rloc],     s_part[mt][0]);
            atomicAdd(&dAl[rloc],     d_part[mt][0]);
            atomicAdd(&sAl[rloc + 8], s_part[mt][1]);
            atomicAdd(&dAl[rloc + 8], d_part[mt][1]);
        }
    }
    __syncthreads();
    if (tid < 128) {
        int r = rowBase + tid;
        if (r < M) {
            g_alphaS[r * heads + head] = sAl[tid];
            g_alphaD[r * heads + head] = dAl[tid];
        }
    }
}

// ---------------------------------------------------------------------------
// Aggregation: one warp per (node, head), online softmax over in-edges.
// h rows are fp16: 64 half = 128 B = ONE cache line; lane i owns elements
// 2i and 2i+1 (one half2 load per lane).
// DST_OUT: write to external out pointer (final layer) vs g_bufB.
// ---------------------------------------------------------------------------
template<int HEADS_T, bool ELU_T, bool ROUND_T, bool DST_OUT>
__global__ void k_agg(float* __restrict__ outExt)
{
    const int stride = HEADS_T * 64;
    float* out = DST_OUT ? outExt : g_bufB;

    int unit = blockIdx.x * (blockDim.x >> 5) + (threadIdx.x >> 5);
    if (unit >= NN * HEADS_T) return;
    int lane = threadIdx.x & 31;
    int n  = unit / HEADS_T;
    int hd = unit - n * HEADS_T;

    int beg = g_rowptr[n], end = g_rowptr[n + 1];
    float ad = g_alphaD[unit];

    float m = -INFINITY, s = 0.f, acc0 = 0.f, acc1 = 0.f;
    for (int i = beg; i < end; i++) {
        int   src = __ldg(&g_csr_src[i]);
        float e   = __ldg(&g_alphaS[src * HEADS_T + hd]) + ad;
        e = (e > 0.f) ? e : 0.2f * e;               // leaky_relu
        float newm = fmaxf(m, e);
        float corr = __expf(m - newm);              // 0 on first iter (m=-inf)
        float p    = __expf(e - newm);
        m = newm;
        s = s * corr + p;
        const __half2* hrow = (const __half2*)(g_bufH + (size_t)src * stride + hd * 64);
        float2 hv = __half22float2(__ldg(&hrow[lane]));
        acc0 = acc0 * corr + p * hv.x;
        acc1 = acc1 * corr + p * hv.y;
    }

    float inv = 1.f / (s + 1e-16f);
    float o0 = acc0 * inv, o1 = acc1 * inv;
    if (beg == end) { o0 = 0.f; o1 = 0.f; }
    if (ELU_T) {
        o0 = (o0 > 0.f) ? o0 : expm1f(o0);
        o1 = (o1 > 0.f) ? o1 : expm1f(o1);
    }
    if (ROUND_T) {
        o0 = __uint_as_float(f2tf(o0));
        o1 = __uint_as_float(f2tf(o1));
    }
    *(float2*)(out + (size_t)n * stride + hd * 64 + lane * 2) = make_float2(o0, o1);
}

// ---------------------------------------------------------------------------
// Launch.  NOTE: launch index 3 is the ncu-profiled slot -> layer-0 GEMM.
// ---------------------------------------------------------------------------
extern "C" void kernel_launch(void* const* d_in, const int* in_sizes, int n_in,
                              void* d_out, int out_size)
{
    const float* x  = (const float*)d_in[0];
    const int*   ei = (const int*)  d_in[1];
    const float* W0 = (const float*)d_in[2];
    const float* a0 = (const float*)d_in[3];
    const float* W1 = (const float*)d_in[4];
    const float* a1 = (const float*)d_in[5];
    const float* W2 = (const float*)d_in[6];
    const float* a2 = (const float*)d_in[7];
    float* out = (float*)d_out;

    const int zb  = (NN + 255) / 256;
    const int eb  = (EE + 255) / 256;
    const int sb  = (NN + 1023) / 1024;
    const dim3 g256(4, (NN + 127) / 128);     // GEMM grid, Ncols=256
    const dim3 g64 (1, (NN + 127) / 128);     // GEMM grid, Ncols=64

    const int W0_OFF = 0;
    const int W1_OFF = 128 * 256;
    const int W2_OFF = 128 * 256 + 256 * 256;

    // launches 0-2: rounding needed by layer-0 GEMM
    k_round<<<1184, 256>>>(x,  1, 0, NN * INDIM);          // 0
    k_round<<<128,  256>>>(W0, 2, W0_OFF, 128 * 256);      // 1
    k_round<<<256,  256>>>(W1, 2, W1_OFF, 256 * 256);      // 2

    // launch 3 (ncu-profiled slot): layer-0 GEMM (+fused alpha)
    k_gemm_tf32<<<g256, 256>>>(W0_OFF, a0, NHEADS, NN, 256, INDIM);   // 3

    k_round<<<64, 256>>>(W2, 2, W2_OFF, 256 * 64);         // 4

    // ---- CSR by dst ----
    k_zero_fill<<<zb, 256>>>();
    k_hist<<<eb, 256>>>(ei);
    k_scan1<<<sb, 1024>>>();
    k_scan2<<<1, 32>>>(sb);
    k_scan3<<<sb, 1024>>>();
    k_zero_fill<<<zb, 256>>>();
    k_scatter<<<eb, 256>>>(ei);

    const int aggWarpsBlk = 8;   // 256 threads
    int units4 = NN * NHEADS;
    int aggBlk4 = (units4 + aggWarpsBlk - 1) / aggWarpsBlk;
    int units1 = NN;
    int aggBlk1 = (units1 + aggWarpsBlk - 1) / aggWarpsBlk;

    // ---- layer 0 agg -> bufB (+ELU, tf32) ----
    k_agg<NHEADS, true, true, false><<<aggBlk4, 256>>>(nullptr);
    // ---- layer 1 ----
    k_gemm_tf32<<<g256, 256>>>(W1_OFF, a1, NHEADS, NN, 256, 256);
    k_agg<NHEADS, true, true, false><<<aggBlk4, 256>>>(nullptr);
    // ---- layer 2 ----
    k_gemm_tf32<<<g64, 256>>>(W2_OFF, a2, 1, NN, 64, 256);
    k_agg<1, false, false, true><<<aggBlk1, 256>>>(out);
}

// round 7
// speedup vs baseline: 1.4812x; 1.4812x over previous
#include <cuda_runtime.h>
#include <math.h>

// Problem constants
#define NN      100000
#define EE      1600000
#define INDIM   128
#define HIDD    64
#define NHEADS  4
#define ODIM    64

// ---------------------------------------------------------------------------
// Scratch (device globals — the sanctioned no-alloc path)
// ---------------------------------------------------------------------------
__device__ float g_bufA[(size_t)NN * 256];   // GEMM outputs h (f32)
__device__ float g_bufB[(size_t)NN * 256];   // agg outputs / rounded x
__device__ float g_wr[128*256 + 256*256 + 256*64];   // tf32-rounded weights
__device__ float g_alphaS[NN * NHEADS];
__device__ float g_alphaD[NN * NHEADS];
__device__ int   g_rowptr[NN + 1];
__device__ int   g_fill[NN];
__device__ int   g_csr_src[EE];
__device__ int   g_bsums[128];

__device__ __forceinline__ unsigned f2tf(float x) {
    unsigned r;
    asm("cvt.rna.tf32.f32 %0, %1;" : "=r"(r) : "f"(x));
    return r;
}

// ---------------------------------------------------------------------------
// tf32 pre-rounding pass (idempotent). dstSel: 1=bufB, 2=g_wr
// ---------------------------------------------------------------------------
__global__ void k_round(const float* __restrict__ src, int dstSel, int dstOff, int n)
{
    float* dst = (dstSel == 2 ? g_wr : g_bufB) + dstOff;
    int i = blockIdx.x * blockDim.x + threadIdx.x;
    int stride = gridDim.x * blockDim.x;
    for (; i < n; i += stride)
        dst[i] = __uint_as_float(f2tf(src[i]));
}

// ---------------------------------------------------------------------------
// CSR build: histogram -> exclusive scan -> scatter
// ---------------------------------------------------------------------------
__global__ void k_zero_fill() {
    int i = blockIdx.x * blockDim.x + threadIdx.x;
    if (i < NN) g_fill[i] = 0;
}

__global__ void k_hist(const int* __restrict__ ei) {
    int e = blockIdx.x * blockDim.x + threadIdx.x;
    if (e < EE) atomicAdd(&g_fill[ei[EE + e]], 1);
}

__global__ void k_scan1() {
    __shared__ int s[1024];
    int t = threadIdx.x;
    int i = blockIdx.x * 1024 + t;
    int v = (i < NN) ? g_fill[i] : 0;
    s[t] = v;
    __syncthreads();
    #pragma unroll
    for (int off = 1; off < 1024; off <<= 1) {
        int add = (t >= off) ? s[t - off] : 0;
        __syncthreads();
        s[t] += add;
        __syncthreads();
    }
    if (i < NN) g_rowptr[i] = s[t] - v;   // exclusive
    if (t == 1023) g_bsums[blockIdx.x] = s[1023];
}

__global__ void k_scan2(int nb) {
    if (threadIdx.x == 0 && blockIdx.x == 0) {
        int run = 0;
        for (int b = 0; b < nb; b++) { int v = g_bsums[b]; g_bsums[b] = run; run += v; }
        g_rowptr[NN] = run;   // == EE
    }
}

__global__ void k_scan3() {
    int i = blockIdx.x * 1024 + threadIdx.x;
    if (i < NN) g_rowptr[i] += g_bsums[blockIdx.x];
}

__global__ void k_scatter(const int* __restrict__ ei) {
    int e = blockIdx.x * blockDim.x + threadIdx.x;
    if (e < EE) {
        int d   = ei[EE + e];
        int pos = g_rowptr[d] + atomicAdd(&g_fill[d], 1);
        g_csr_src[pos] = ei[e];
    }
}

// ---------------------------------------------------------------------------
// Common GEMM helpers
// ---------------------------------------------------------------------------
__device__ __forceinline__ void mma_tf32(float* c, const unsigned* a, const unsigned* b) {
    asm volatile(
        "mma.sync.aligned.m16n8k8.row.col.f32.tf32.tf32.f32 "
        "{%0,%1,%2,%3}, {%4,%5,%6,%7}, {%8,%9}, {%0,%1,%2,%3};\n"
        : "+f"(c[0]), "+f"(c[1]), "+f"(c[2]), "+f"(c[3])
        : "r"(a[0]), "r"(a[1]), "r"(a[2]), "r"(a[3]), "r"(b[0]), "r"(b[1]));
}

__device__ __forceinline__ void cp16(void* smem, const void* gmem, bool pred) {
    unsigned saddr = (unsigned)__cvta_generic_to_shared(smem);
    int sz = pred ? 16 : 0;   // src-size 0 => zero-fill
    asm volatile("cp.async.cg.shared.global [%0], [%1], 16, %2;\n"
                 :: "r"(saddr), "l"(gmem), "r"(sz));
}

// ---------------------------------------------------------------------------
// BN=128 GEMM: BM=128, BN=128, BK=16, 2-stage cp.async. 8 warps (2 M x 4 N),
// warp tile 64x32 (mt=4, nt=4): 24 LDS / 16 MMAs per k-step (was 2.0/MMA).
// Block covers 2 heads (cols 0..63 = head 2*bx, 64..127 = head 2*bx+1);
// fused alpha epilogue for both. A,B pre-rounded tf32.
// ---------------------------------------------------------------------------
__global__ void __launch_bounds__(256)
k_gemm_bn128(int wOff, const float* __restrict__ aVec, int heads,
             int M, int Ncols, int K)
{
    const float* A = g_bufB;
    const float* B = g_wr + wOff;
    float* C = g_bufA;

    __shared__ float As[2][128][20];    // [stage][m][k]  20480 B
    __shared__ float Bs[2][16][136];    // [stage][k][n]  17408 B
    __shared__ float a_sh[2][128];      // per head: a_s(0..63)|a_d(64..127)
    __shared__ float sAl[256], dAl[256];   // [head_local*128 + row]

    int tid  = threadIdx.x;
    int lane = tid & 31;
    int wid  = tid >> 5;
    int warp_m = wid & 1;      // 0..1, 64 rows each
    int warp_n = wid >> 1;     // 0..3, 32 cols each
    int rowBase = blockIdx.y * 128;
    int colBase = blockIdx.x * 128;
    int headBase = blockIdx.x * 2;

    {
        int hl = tid >> 7, c = tid & 127;
        a_sh[hl][c] = aVec[(headBase + hl) * 128 + c];
        sAl[tid] = 0.f;
        dAl[tid] = 0.f;
    }

    // async-load coords
    int ar = tid >> 2;          // 0..63 (rows ar, ar+64)
    int ak = (tid & 3) * 4;     // 0,4,8,12
    int br = tid >> 4;          // 0..15
    int bc = (tid & 15) * 8;    // 0..120 (two float4: bc, bc+4)

    const float* aSrc0 = A + (size_t)(rowBase + ar) * K + ak;
    const float* aSrc1 = A + (size_t)(rowBase + ar + 64) * K + ak;
    const float* bSrc  = B + (size_t)br * Ncols + colBase + bc;
    bool aOk0 = (rowBase + ar)      < M;
    bool aOk1 = (rowBase + ar + 64) < M;

    float acc[4][4][4];
    #pragma unroll
    for (int mt = 0; mt < 4; mt++)
        #pragma unroll
        for (int nt = 0; nt < 4; nt++)
            #pragma unroll
            for (int i = 0; i < 4; i++) acc[mt][nt][i] = 0.f;

    int nIter = K >> 4;

    cp16(&As[0][ar][ak],      aSrc0, aOk0);
    cp16(&As[0][ar + 64][ak], aSrc1, aOk1);
    cp16(&Bs[0][br][bc],      bSrc,     true);
    cp16(&Bs[0][br][bc + 4],  bSrc + 4, true);
    asm volatile("cp.async.commit_group;\n" ::: "memory");

    for (int it = 0; it < nIter; it++) {
        int s = it & 1;
        if (it + 1 < nIter) {
            int k0n = (it + 1) << 4;
            cp16(&As[s ^ 1][ar][ak],      aSrc0 + k0n, aOk0);
            cp16(&As[s ^ 1][ar + 64][ak], aSrc1 + k0n, aOk1);
            const float* bs = bSrc + (size_t)k0n * Ncols;
            cp16(&Bs[s ^ 1][br][bc],      bs,     true);
            cp16(&Bs[s ^ 1][br][bc + 4],  bs + 4, true);
            asm volatile("cp.async.commit_group;\n" ::: "memory");
            asm volatile("cp.async.wait_group 1;\n" ::: "memory");
        } else {
            asm volatile("cp.async.wait_group 0;\n" ::: "memory");
        }
        __syncthreads();

        #pragma unroll
        for (int kk = 0; kk < 16; kk += 8) {
            unsigned af[4][4], bf[4][2];
            #pragma unroll
            for (int mt = 0; mt < 4; mt++) {
                int r0 = warp_m * 64 + mt * 16 + (lane >> 2);
                int kc = kk + (lane & 3);
                af[mt][0] = __float_as_uint(As[s][r0][kc]);
                af[mt][1] = __float_as_uint(As[s][r0 + 8][kc]);
                af[mt][2] = __float_as_uint(As[s][r0][kc + 4]);
                af[mt][3] = __float_as_uint(As[s][r0 + 8][kc + 4]);
            }
            #pragma unroll
            for (int nt = 0; nt < 4; nt++) {
                int cn = warp_n * 32 + nt * 8 + (lane >> 2);
                bf[nt][0] = __float_as_uint(Bs[s][kk + (lane & 3)][cn]);
                bf[nt][1] = __float_as_uint(Bs[s][kk + (lane & 3) + 4][cn]);
            }
            #pragma unroll
            for (int mt = 0; mt < 4; mt++)
                #pragma unroll
                for (int nt = 0; nt < 4; nt++)
                    mma_tf32(acc[mt][nt], af[mt], bf[nt]);
        }
        __syncthreads();
    }

    // ---- Epilogue: store C (f32) + fused alpha for 2 heads ----
    int head_local = warp_n >> 1;           // warp covers one head
    float s_part[4][2], d_part[4][2];
    #pragma unroll
    for (int mt = 0; mt < 4; mt++) { s_part[mt][0]=s_part[mt][1]=0.f; d_part[mt][0]=d_part[mt][1]=0.f; }

    #pragma unroll
    for (int mt = 0; mt < 4; mt++) {
        int r0 = rowBase + warp_m * 64 + mt * 16 + (lane >> 2);
        #pragma unroll
        for (int nt = 0; nt < 4; nt++) {
            int cn  = warp_n * 32 + nt * 8 + (lane & 3) * 2;  // block-local col
            int c0  = colBase + cn;
            int chn = (warp_n & 1) * 32 + nt * 8 + (lane & 3) * 2; // col in head
            if (r0 < M) {
                float2 v = make_float2(acc[mt][nt][0], acc[mt][nt][1]);
                *(float2*)(C + (size_t)r0 * Ncols + c0) = v;
            }
            if (r0 + 8 < M) {
                float2 v = make_float2(acc[mt][nt][2], acc[mt][nt][3]);
                *(float2*)(C + (size_t)(r0 + 8) * Ncols + c0) = v;
            }
            float as0 = a_sh[head_local][chn],      as1 = a_sh[head_local][chn + 1];
            float ad0 = a_sh[head_local][64 + chn], ad1 = a_sh[head_local][64 + chn + 1];
            s_part[mt][0] += acc[mt][nt][0] * as0 + acc[mt][nt][1] * as1;
            d_part[mt][0] += acc[mt][nt][0] * ad0 + acc[mt][nt][1] * ad1;
            s_part[mt][1] += acc[mt][nt][2] * as0 + acc[mt][nt][3] * as1;
            d_part[mt][1] += acc[mt][nt][2] * ad0 + acc[mt][nt][3] * ad1;
        }
    }
    #pragma unroll
    for (int mt = 0; mt < 4; mt++)
        #pragma unroll
        for (int sl = 0; sl < 2; sl++) {
            #pragma unroll
            for (int o = 1; o < 4; o <<= 1) {
                s_part[mt][sl] += __shfl_xor_sync(0xffffffffu, s_part[mt][sl], o);
                d_part[mt][sl] += __shfl_xor_sync(0xffffffffu, d_part[mt][sl], o);
            }
        }
    if ((lane & 3) == 0) {
        #pragma unroll
        for (int mt = 0; mt < 4; mt++) {
            int rloc = warp_m * 64 + mt * 16 + (lane >> 2);
            atomicAdd(&sAl[head_local * 128 + rloc],     s_part[mt][0]);
            atomicAdd(&dAl[head_local * 128 + rloc],     d_part[mt][0]);
            atomicAdd(&sAl[head_local * 128 + rloc + 8], s_part[mt][1]);
            atomicAdd(&dAl[head_local * 128 + rloc + 8], d_part[mt][1]);
        }
    }
    __syncthreads();
    if (tid < 128) {
        int r = rowBase + tid;
        if (r < M) {
            #pragma unroll
            for (int hl = 0; hl < 2; hl++) {
                g_alphaS[r * heads + headBase + hl] = sAl[hl * 128 + tid];
                g_alphaD[r * heads + headBase + hl] = dAl[hl * 128 + tid];
            }
        }
    }
}

// ---------------------------------------------------------------------------
// BN=64 GEMM (layer 2): the proven R5 kernel. BM=128, 8 warps (4 M x 2 N),
// warp tile 32x32; fused alpha for the single head.
// ---------------------------------------------------------------------------
__global__ void __launch_bounds__(256)
k_gemm_bn64(int wOff, const float* __restrict__ aVec, int heads,
            int M, int Ncols, int K)
{
    const float* A = g_bufB;
    const float* B = g_wr + wOff;
    float* C = g_bufA;

    __shared__ float As[2][128][20];
    __shared__ float Bs[2][16][72];
    __shared__ float a_sh[128];
    __shared__ float sAl[128], dAl[128];

    int tid  = threadIdx.x;
    int lane = tid & 31;
    int wid  = tid >> 5;
    int warp_m = wid & 3;
    int warp_n = wid >> 2;
    int rowBase = blockIdx.y * 128;
    int colBase = blockIdx.x * 64;
    int head    = blockIdx.x;

    if (tid < 128) {
        a_sh[tid] = aVec[head * 128 + tid];
        sAl[tid] = 0.f;
        dAl[tid] = 0.f;
    }

    int ar = tid >> 2;
    int ak = (tid & 3) * 4;
    int br = tid >> 4;
    int bc = (tid & 15) * 4;

    const float* aSrc0 = A + (size_t)(rowBase + ar) * K + ak;
    const float* aSrc1 = A + (size_t)(rowBase + ar + 64) * K + ak;
    const float* bSrc  = B + (size_t)br * Ncols + colBase + bc;
    bool aOk0 = (rowBase + ar)      < M;
    bool aOk1 = (rowBase + ar + 64) < M;

    float acc[2][4][4];
    #pragma unroll
    for (int mt = 0; mt < 2; mt++)
        #pragma unroll
        for (int nt = 0; nt < 4; nt++)
            #pragma unroll
            for (int i = 0; i < 4; i++) acc[mt][nt][i] = 0.f;

    int nIter = K >> 4;

    cp16(&As[0][ar][ak],      aSrc0, aOk0);
    cp16(&As[0][ar + 64][ak], aSrc1, aOk1);
    cp16(&Bs[0][br][bc],      bSrc,  true);
    asm volatile("cp.async.commit_group;\n" ::: "memory");

    for (int it = 0; it < nIter; it++) {
        int s = it & 1;
        if (it + 1 < nIter) {
            int k0n = (it + 1) << 4;
            cp16(&As[s ^ 1][ar][ak],      aSrc0 + k0n, aOk0);
            cp16(&As[s ^ 1][ar + 64][ak], aSrc1 + k0n, aOk1);
            cp16(&Bs[s ^ 1][br][bc],      bSrc + (size_t)k0n * Ncols, true);
            asm volatile("cp.async.commit_group;\n" ::: "memory");
            asm volatile("cp.async.wait_group 1;\n" ::: "memory");
        } else {
            asm volatile("cp.async.wait_group 0;\n" ::: "memory");
        }
        __syncthreads();

        #pragma unroll
        for (int kk = 0; kk < 16; kk += 8) {
            unsigned af[2][4], bf[4][2];
            #pragma unroll
            for (int mt = 0; mt < 2; mt++) {
                int r0 = warp_m * 32 + mt * 16 + (lane >> 2);
                int kc = kk + (lane & 3);
                af[mt][0] = __float_as_uint(As[s][r0][kc]);
                af[mt][1] = __float_as_uint(As[s][r0 + 8][kc]);
                af[mt][2] = __float_as_uint(As[s][r0][kc + 4]);
                af[mt][3] = __float_as_uint(As[s][r0 + 8][kc + 4]);
            }
            #pragma unroll
            for (int nt = 0; nt < 4; nt++) {
                int cn = warp_n * 32 + nt * 8 + (lane >> 2);
                bf[nt][0] = __float_as_uint(Bs[s][kk + (lane & 3)][cn]);
                bf[nt][1] = __float_as_uint(Bs[s][kk + (lane & 3) + 4][cn]);
            }
            #pragma unroll
            for (int mt = 0; mt < 2; mt++)
                #pragma unroll
                for (int nt = 0; nt < 4; nt++)
                    mma_tf32(acc[mt][nt], af[mt], bf[nt]);
        }
        __syncthreads();
    }

    float s_part[2][2] = {{0.f,0.f},{0.f,0.f}};
    float d_part[2][2] = {{0.f,0.f},{0.f,0.f}};

    #pragma unroll
    for (int mt = 0; mt < 2; mt++) {
        int r0 = rowBase + warp_m * 32 + mt * 16 + (lane >> 2);
        #pragma unroll
        for (int nt = 0; nt < 4; nt++) {
            int cn = warp_n * 32 + nt * 8 + (lane & 3) * 2;
            int c0 = colBase + cn;
            if (r0 < M) {
                float2 v = make_float2(acc[mt][nt][0], acc[mt][nt][1]);
                *(float2*)(C + (size_t)r0 * Ncols + c0) = v;
            }
            if (r0 + 8 < M) {
                float2 v = make_float2(acc[mt][nt][2], acc[mt][nt][3]);
                *(float2*)(C + (size_t)(r0 + 8) * Ncols + c0) = v;
            }
            float as0 = a_sh[cn], as1 = a_sh[cn + 1];
            float ad0 = a_sh[64 + cn], ad1 = a_sh[64 + cn + 1];
            s_part[mt][0] += acc[mt][nt][0] * as0 + acc[mt][nt][1] * as1;
            d_part[mt][0] += acc[mt][nt][0] * ad0 + acc[mt][nt][1] * ad1;
            s_part[mt][1] += acc[mt][nt][2] * as0 + acc[mt][nt][3] * as1;
            d_part[mt][1] += acc[mt][nt][2] * ad0 + acc[mt][nt][3] * ad1;
        }
    }
    #pragma unroll
    for (int mt = 0; mt < 2; mt++)
        #pragma unroll
        for (int sl = 0; sl < 2; sl++) {
            #pragma unroll
            for (int o = 1; o < 4; o <<= 1) {
                s_part[mt][sl] += __shfl_xor_sync(0xffffffffu, s_part[mt][sl], o);
                d_part[mt][sl] += __shfl_xor_sync(0xffffffffu, d_part[mt][sl], o);
            }
        }
    if ((lane & 3) == 0) {
        #pragma unroll
        for (int mt = 0; mt < 2; mt++) {
            int rloc = warp_m * 32 + mt * 16 + (lane >> 2);
            atomicAdd(&sAl[rloc],     s_part[mt][0]);
            atomicAdd(&dAl[rloc],     d_part[mt][0]);
            atomicAdd(&sAl[rloc + 8], s_part[mt][1]);
            atomicAdd(&dAl[rloc + 8], d_part[mt][1]);
        }
    }
    __syncthreads();
    if (tid < 128) {
        int r = rowBase + tid;
        if (r < M) {
            g_alphaS[r * heads + head] = sAl[tid];
            g_alphaD[r * heads + head] = dAl[tid];
        }
    }
}

// ---------------------------------------------------------------------------
// Aggregation: one warp per (node, head), online softmax over in-edges.
// (exact R5 version: f32 h in g_bufA, strided lane / lane+32 loads)
// ---------------------------------------------------------------------------
template<int HEADS_T, bool ELU_T, bool ROUND_T, bool DST_OUT>
__global__ void k_agg(float* __restrict__ outExt)
{
    const float* h = g_bufA;
    float* out = DST_OUT ? outExt : g_bufB;
    const int stride = HEADS_T * 64;

    int unit = blockIdx.x * (blockDim.x >> 5) + (threadIdx.x >> 5);
    if (unit >= NN * HEADS_T) return;
    int lane = threadIdx.x & 31;
    int n  = unit / HEADS_T;
    int hd = unit - n * HEADS_T;

    int beg = g_rowptr[n], end = g_rowptr[n + 1];
    float ad = g_alphaD[unit];

    float m = -INFINITY, s = 0.f, acc0 = 0.f, acc1 = 0.f;
    for (int i = beg; i < end; i++) {
        int   src = __ldg(&g_csr_src[i]);
        float e   = __ldg(&g_alphaS[src * HEADS_T + hd]) + ad;
        e = (e > 0.f) ? e : 0.2f * e;               // leaky_relu
        float newm = fmaxf(m, e);
        float corr = __expf(m - newm);
        float p    = __expf(e - newm);
        m = newm;
        s = s * corr + p;
        const float* hrow = h + (size_t)src * stride + hd * 64;
        acc0 = acc0 * corr + p * __ldg(&hrow[lane]);
        acc1 = acc1 * corr + p * __ldg(&hrow[lane + 32]);
    }

    float inv = 1.f / (s + 1e-16f);
    float o0 = acc0 * inv, o1 = acc1 * inv;
    if (beg == end) { o0 = 0.f; o1 = 0.f; }
    if (ELU_T) {
        o0 = (o0 > 0.f) ? o0 : expm1f(o0);
        o1 = (o1 > 0.f) ? o1 : expm1f(o1);
    }
    if (ROUND_T) {
        o0 = __uint_as_float(f2tf(o0));
        o1 = __uint_as_float(f2tf(o1));
    }
    out[(size_t)n * stride + hd * 64 + lane]      = o0;
    out[(size_t)n * stride + hd * 64 + lane + 32] = o1;
}

// ---------------------------------------------------------------------------
// Launch. Launch index 3 = ncu-profiled slot -> layer-0 GEMM (bn128).
// ---------------------------------------------------------------------------
extern "C" void kernel_launch(void* const* d_in, const int* in_sizes, int n_in,
                              void* d_out, int out_size)
{
    const float* x  = (const float*)d_in[0];
    const int*   ei = (const int*)  d_in[1];
    const float* W0 = (const float*)d_in[2];
    const float* a0 = (const float*)d_in[3];
    const float* W1 = (const float*)d_in[4];
    const float* a1 = (const float*)d_in[5];
    const float* W2 = (const float*)d_in[6];
    const float* a2 = (const float*)d_in[7];
    float* out = (float*)d_out;

    const int zb  = (NN + 255) / 256;
    const int eb  = (EE + 255) / 256;
    const int sb  = (NN + 1023) / 1024;
    const dim3 gBig(2, (NN + 127) / 128);     // bn128 grid, Ncols=256
    const dim3 gS  (1, (NN + 127) / 128);     // bn64 grid,  Ncols=64

    const int W0_OFF = 0;
    const int W1_OFF = 128 * 256;
    const int W2_OFF = 128 * 256 + 256 * 256;

    // launches 0-2: rounding needed by layer-0 GEMM
    k_round<<<1184, 256>>>(x,  1, 0, NN * INDIM);          // 0
    k_round<<<128,  256>>>(W0, 2, W0_OFF, 128 * 256);      // 1
    k_round<<<256,  256>>>(W1, 2, W1_OFF, 256 * 256);      // 2

    // launch 3 (profiled): layer-0 GEMM (+fused alpha)
    k_gemm_bn128<<<gBig, 256>>>(W0_OFF, a0, NHEADS, NN, 256, INDIM);  // 3

    k_round<<<64, 256>>>(W2, 2, W2_OFF, 256 * 64);         // 4

    // ---- CSR by dst ----
    k_zero_fill<<<zb, 256>>>();
    k_hist<<<eb, 256>>>(ei);
    k_scan1<<<sb, 1024>>>();
    k_scan2<<<1, 32>>>(sb);
    k_scan3<<<sb, 1024>>>();
    k_zero_fill<<<zb, 256>>>();
    k_scatter<<<eb, 256>>>(ei);

    const int aggWarpsBlk = 8;   // 256 threads
    int units4 = NN * NHEADS;
    int aggBlk4 = (units4 + aggWarpsBlk - 1) / aggWarpsBlk;
    int units1 = NN;
    int aggBlk1 = (units1 + aggWarpsBlk - 1) / aggWarpsBlk;

    // ---- layer 0 agg -> bufB (+ELU, tf32) ----
    k_agg<NHEADS, true, true, false><<<aggBlk4, 256>>>(nullptr);
    // ---- layer 1 ----
    k_gemm_bn128<<<gBig, 256>>>(W1_OFF, a1, NHEADS, NN, 256, 256);
    k_agg<NHEADS, true, true, false><<<aggBlk4, 256>>>(nullptr);
    // ---- layer 2 ----
    k_gemm_bn64<<<gS, 256>>>(W2_OFF, a2, 1, NN, 64, 256);
    k_agg<1, false, false, true><<<aggBlk1, 256>>>(out);
}